// round 10
// baseline (speedup 1.0000x reference)
#include <cuda_runtime.h>
#include <cuda_bf16.h>
#include <math.h>
#include <stdint.h>

// ---------------- problem constants ----------------
#define BB 16
#define CC 16
#define HH 256
#define WW 256
#define NGF 16
#define PLANE 65536
#define NPIX (BB*PLANE)

// ---------------- conv tiling ----------------
#define TW 32                 // tile width (px)
#define TH 8                  // tile height
#define MPX (TW*TH)           // 256 M rows
#define HALO_H 10
#define HALO_W 34
#define CI 48
#define CI_PAD 56             // bf16 elems per pixel (112 B)
#define PIX_STRIDE 112        // bytes
#define CO 64
#define CO_PAD 72             // bf16 elems per weight row (144 B)
#define W_ROW 144             // bytes
#define TAPS 9
#define IN_BYTES (HALO_H*HALO_W*PIX_STRIDE)      // 38,080
#define W_BYTES  (TAPS*CI*W_ROW)                 // 62,208
#define DYN_SMEM 100352
#define CONV_THREADS 256
#define NWARPS (CONV_THREADS/32)

#define STATS_BLOCKS 592

// ---------------- device scratch ----------------
__device__ double g_part[STATS_BLOCKS*5];
__device__ float  g_coef[3][NGF];
__device__ float  g_off[BB*2*PLANE];
__device__ __align__(16) unsigned short g_wb[TAPS*CI*CO_PAD];   // bf16 bits

// ---------------- helpers ----------------
__device__ __forceinline__ uint32_t smem_u32(const void* p) {
    uint32_t a;
    asm("{ .reg .u64 t; cvta.to.shared.u64 t, %1; cvt.u32.u64 %0, t; }"
        : "=r"(a) : "l"(p));
    return a;
}
__device__ __forceinline__ void ldm_x4(uint32_t r[4], uint32_t addr) {
    asm volatile("ldmatrix.sync.aligned.m8n8.x4.shared.b16 {%0,%1,%2,%3}, [%4];"
        : "=r"(r[0]), "=r"(r[1]), "=r"(r[2]), "=r"(r[3]) : "r"(addr));
}
__device__ __forceinline__ void ldm_x2t(uint32_t r[2], uint32_t addr) {
    asm volatile("ldmatrix.sync.aligned.m8n8.x2.trans.shared.b16 {%0,%1}, [%2];"
        : "=r"(r[0]), "=r"(r[1]) : "r"(addr));
}
__device__ __forceinline__ void mma_bf16(float d[4], const uint32_t a[4],
                                         const uint32_t b[2]) {
    asm volatile(
        "mma.sync.aligned.m16n8k16.row.col.f32.bf16.bf16.f32 "
        "{%0,%1,%2,%3}, {%4,%5,%6,%7}, {%8,%9}, {%0,%1,%2,%3};"
        : "+f"(d[0]), "+f"(d[1]), "+f"(d[2]), "+f"(d[3])
        : "r"(a[0]), "r"(a[1]), "r"(a[2]), "r"(a[3]), "r"(b[0]), "r"(b[1]));
}
__inline__ __device__ double warp_sum(double v) {
    #pragma unroll
    for (int o = 16; o > 0; o >>= 1) v += __shfl_down_sync(0xffffffffu, v, o);
    return v;
}

// ---------------------------------------------------------------------------
// K1: 5-stat partial reduction over pre_offset (no atomics; per-block partials)
// ---------------------------------------------------------------------------
__global__ void stats_kernel(const float* __restrict__ pre) {
    double s[5] = {0, 0, 0, 0, 0};
    for (int i = blockIdx.x * blockDim.x + threadIdx.x; i < NPIX;
         i += gridDim.x * blockDim.x) {
        int b = i >> 16;
        int p = i & 65535;
        float p0 = pre[(b * 2) * PLANE + p];
        float p1 = pre[(b * 2 + 1) * PLANE + p];
        s[0] += p0; s[1] += p1;
        s[2] += (double)p0 * p0;
        s[3] += (double)p0 * p1;
        s[4] += (double)p1 * p1;
    }
    __shared__ double sh[8][5];
    const int w = threadIdx.x >> 5, l = threadIdx.x & 31;
    #pragma unroll
    for (int q = 0; q < 5; q++) {
        double v = warp_sum(s[q]);
        if (l == 0) sh[w][q] = v;
    }
    __syncthreads();
    if (threadIdx.x == 0) {
        #pragma unroll
        for (int q = 0; q < 5; q++) {
            double t = 0;
            for (int ww = 0; ww < 8; ww++) t += sh[ww][q];
            g_part[blockIdx.x * 5 + q] = t;
        }
    }
}

// ---------------------------------------------------------------------------
// K2: final reduce + fold 1x1 conv + BatchNorm into per-channel affine coefs
// ---------------------------------------------------------------------------
__global__ void coef2_kernel(const float* __restrict__ embW,
                             const float* __restrict__ embB,
                             const float* __restrict__ gamma,
                             const float* __restrict__ beta) {
    __shared__ double st[5];
    const int w = threadIdx.x >> 5, l = threadIdx.x & 31;
    if (w < 5) {
        double s = 0;
        for (int i = l; i < STATS_BLOCKS; i += 32) s += g_part[i * 5 + w];
        s = warp_sum(s);
        if (l == 0) st[w] = s;
    }
    __syncthreads();
    const int c = threadIdx.x;
    if (c >= NGF) return;
    const double N = (double)NPIX;
    double m0 = st[0] / N, m1 = st[1] / N;
    double v00 = st[2] / N - m0 * m0;
    double v01 = st[3] / N - m0 * m1;
    double v11 = st[4] / N - m1 * m1;
    double w0 = embW[c * 2 + 0], w1 = embW[c * 2 + 1];
    double var = w0 * w0 * v00 + 2.0 * w0 * w1 * v01 + w1 * w1 * v11;
    double mu = w0 * m0 + w1 * m1 + (double)embB[c];
    double scale = (double)gamma[c] * rsqrt(var + 1e-5);
    g_coef[0][c] = (float)(scale * w0);
    g_coef[1][c] = (float)(scale * w1);
    g_coef[2][c] = (float)((double)beta[c] + scale * ((double)embB[c] - mu));
}

// ---------------------------------------------------------------------------
// K3a: weight prep — fp32 [64co][48ci][3][3] -> bf16 [tap][ci][co_pad 72]
// ---------------------------------------------------------------------------
__global__ void prep_w_kernel(const float* __restrict__ lstmW) {
    int i = blockIdx.x * blockDim.x + threadIdx.x;
    if (i >= TAPS * CI * CO_PAD) return;
    int tap = i / (CI * CO_PAD);
    int r = i - tap * (CI * CO_PAD);
    int ci = r / CO_PAD;
    int co = r - ci * CO_PAD;
    float v = (co < CO) ? lstmW[co * (CI * 9) + ci * 9 + tap] : 0.f;
    g_wb[i] = __bfloat16_as_ushort(__float2bfloat16(v));
}

// ---------------------------------------------------------------------------
// K3b: HMMA fused conv + gates + offset head.
// CTA = 256 threads, 32x8 px tile, GEMM M=256 N=64 K=432. Grid = 4096.
// 2 CTAs/SM (smem 100KB, regs ~32k each) -> staging/compute overlap.
// Warp tile: 64 px x 32 co  (wm = wid>>1 in 0..3, wn = wid&1).
// ---------------------------------------------------------------------------
extern __shared__ uint8_t cv_smem[];

__global__ void __launch_bounds__(CONV_THREADS, 2)
tconv_kernel(const float* __restrict__ x, const float* __restrict__ pre,
             const float* __restrict__ h0, const float* __restrict__ c0,
             const float* __restrict__ outW, const float* __restrict__ outB) {
    const int tid = threadIdx.x;
    const int lane = tid & 31;
    const int wid = tid >> 5;
    const int b = blockIdx.z;
    const int x0 = blockIdx.x * TW;
    const int y0 = blockIdx.y * TH;

    __nv_bfloat16* in_s16 = (__nv_bfloat16*)cv_smem;
    uint8_t* w_s = cv_smem + IN_BYTES;

    // ---- stage weights (L2-resident source) ----
    {
        const uint4* src = (const uint4*)g_wb;
        uint4* dst = (uint4*)w_s;
        #pragma unroll
        for (int i = tid; i < W_BYTES / 16; i += CONV_THREADS) dst[i] = src[i];
    }

    // ---- stage input tile, channel-last [y][x][ci] (thread per (y,ci),
    //      per-thread sequential x sweep — round-4 proven layout) ----
    for (int t = tid; t < HALO_H * CI; t += CONV_THREADS) {
        int y = t / CI, ci = t - y * CI;
        int gy = y0 + y - 1;
        bool yok = (gy >= 0 && gy < HH);
        const float* srcp;
        float ca = 0.f, cb2 = 0.f, cd = 0.f;
        int mode;
        if (ci < 16) { mode = 0; srcp = x + (b * 16 + ci) * PLANE; }
        else if (ci < 32) {
            mode = 1;
            int ce = ci - 16;
            ca = g_coef[0][ce]; cb2 = g_coef[1][ce]; cd = g_coef[2][ce];
            srcp = pre + (b * 2) * PLANE;
        } else { mode = 2; srcp = h0 + (b * 16 + (ci - 32)) * PLANE; }

        #pragma unroll 2
        for (int xi = 0; xi < HALO_W; xi++) {
            int gx = x0 + xi - 1;
            float v = 0.f;
            if (yok && gx >= 0 && gx < WW) {
                int pix = gy * WW + gx;
                if (mode == 1) {
                    float p0 = srcp[pix];
                    float p1 = srcp[PLANE + pix];
                    float e = fmaf(ca, p0, fmaf(cb2, p1, cd));
                    v = e > 0.f ? e : 0.2f * e;
                } else {
                    v = srcp[pix];
                }
            }
            in_s16[(y * HALO_W + xi) * CI_PAD + ci] = __float2bfloat16(v);
        }
    }
    __syncthreads();

    // ---- main HMMA loop ----
    const int wm = wid >> 1;          // 0..3 : M block of 64 px (4 m16 tiles)
    const int wn = wid & 1;           // 0..1 : co group of 32

    float d[4][4][4];
    #pragma unroll
    for (int mt = 0; mt < 4; mt++)
        #pragma unroll
        for (int nt = 0; nt < 4; nt++)
            #pragma unroll
            for (int q = 0; q < 4; q++) d[mt][nt][q] = 0.f;

    const uint32_t in_base = smem_u32(cv_smem);
    const uint32_t w_base = in_base + IN_BYTES + (uint32_t)(wn * 32) * 2;
    const int ar = lane & 15;         // A matrix row within tile
    const int kh = lane >> 4;         // A k-half

    #pragma unroll 1
    for (int tap = 0; tap < TAPS; tap++) {
        const int dy = tap / 3 - 1, dx = tap % 3 - 1;
        #pragma unroll
        for (int cig = 0; cig < 3; cig++) {
            uint32_t baddr = w_base +
                (uint32_t)(tap * (CI * W_ROW) + (cig * 16 + (lane & 15)) * W_ROW);
            uint32_t bf[4][2];
            ldm_x2t(bf[0], baddr);
            ldm_x2t(bf[1], baddr + 16);
            ldm_x2t(bf[2], baddr + 32);
            ldm_x2t(bf[3], baddr + 48);
            #pragma unroll
            for (int mt = 0; mt < 4; mt++) {
                const int gmt = wm * 4 + mt;            // 16-px tile index 0..15
                const int y_in = (gmt >> 1) + dy + 1;
                const int x_in = (gmt & 1) * 16 + ar + dx + 1;
                uint32_t aaddr = in_base +
                    (uint32_t)((y_in * HALO_W + x_in) * PIX_STRIDE
                               + cig * 32 + kh * 16);
                uint32_t a[4];
                ldm_x4(a, aaddr);
                mma_bf16(d[mt][0], a, bf[0]);
                mma_bf16(d[mt][1], a, bf[1]);
                mma_bf16(d[mt][2], a, bf[2]);
                mma_bf16(d[mt][3], a, bf[3]);
            }
        }
    }
    __syncthreads();

    // ---- exchange D through smem: A_ex[px][co], stride 65 ----
    float* A_ex = (float*)cv_smem;
    {
        const int row0 = lane >> 2;
        const int colb = (lane & 3) * 2;
        #pragma unroll
        for (int mt = 0; mt < 4; mt++) {
            const int gmt = wm * 4 + mt;
            #pragma unroll
            for (int nt = 0; nt < 4; nt++) {
                const int co = wn * 32 + nt * 8 + colb;
                const int p0 = gmt * 16 + row0;
                A_ex[p0 * 65 + co]       = d[mt][nt][0];
                A_ex[p0 * 65 + co + 1]   = d[mt][nt][1];
                A_ex[(p0 + 8) * 65 + co]     = d[mt][nt][2];
                A_ex[(p0 + 8) * 65 + co + 1] = d[mt][nt][3];
            }
        }
    }
    __syncthreads();

    // ---- gates + offset head, one pixel per thread ----
    {
        const int p = tid;
        const int py = y0 + (p >> 5);
        const int pxx = x0 + (p & 31);
        const int pix = py * WW + pxx;
        const float* Ap = A_ex + p * 65;
        float off0 = outB[0], off1 = outB[1];
        #pragma unroll
        for (int ch = 0; ch < 16; ch++) {
            float ai = Ap[ch];
            float af = Ap[16 + ch];
            float ao = Ap[32 + ch];
            float ag = Ap[48 + ch];
            float iv = 1.f / (1.f + __expf(-ai));
            float fv = 1.f / (1.f + __expf(-af));
            float ov = 1.f / (1.f + __expf(-ao));
            float gv = tanhf(ag);
            float c0v = c0[(b * 16 + ch) * PLANE + pix];
            float c1 = fv * c0v + iv * gv;
            float hv = ov * tanhf(c1);
            off0 = fmaf(outW[ch], hv, off0);
            off1 = fmaf(outW[16 + ch], hv, off1);
        }
        g_off[(b * 2) * PLANE + pix] = off0;
        g_off[(b * 2 + 1) * PLANE + pix] = off1;
    }
}

// ---------------------------------------------------------------------------
// K4: bilinear warp (torch-.view pair semantics: flat indices 2p, 2p+1)
// ---------------------------------------------------------------------------
__global__ void sample_kernel(const float* __restrict__ x,
                              float* __restrict__ out) {
    int n = blockIdx.x * blockDim.x + threadIdx.x;
    int pix = n & 65535;
    int bc = n >> 16;
    int b = bc >> 4;
    int hh = pix >> 8;
    int ww = pix & 255;

    const float2* offb = (const float2*)(g_off + b * 2 * PLANE);
    float2 offp = offb[pix];
    float off0 = offp.x;
    float off1 = offp.y;

    float yc = fminf(fmaxf((float)hh + off0, 0.f), 255.f);
    float xc = fminf(fmaxf((float)ww + off1, 0.f), 255.f);
    float y0f = floorf(yc);
    float x0f = floorf(xc);
    int y0 = (int)y0f;
    int x0 = (int)x0f;
    int y1 = min(y0 + 1, 255);
    int x1 = min(x0 + 1, 255);
    float dy = yc - y0f;
    float dx = xc - x0f;

    const float* img = x + bc * PLANE;
    float v00 = img[y0 * WW + x0];
    float v01 = img[y0 * WW + x1];
    float v10 = img[y1 * WW + x0];
    float v11 = img[y1 * WW + x1];
    float top = v00 + (v01 - v00) * dx;
    float bot = v10 + (v11 - v10) * dx;
    out[n] = top + (bot - top) * dy;
}

// ---------------------------------------------------------------------------
extern "C" void kernel_launch(void* const* d_in, const int* in_sizes, int n_in,
                              void* d_out, int out_size) {
    const float* x     = (const float*)d_in[0];
    const float* pre   = (const float*)d_in[1];
    const float* h0    = (const float*)d_in[2];
    const float* c0    = (const float*)d_in[3];
    const float* embW  = (const float*)d_in[4];
    const float* embB  = (const float*)d_in[5];
    const float* gamma = (const float*)d_in[6];
    const float* beta  = (const float*)d_in[7];
    const float* lstmW = (const float*)d_in[8];
    const float* outW  = (const float*)d_in[9];
    const float* outB  = (const float*)d_in[10];
    float* out = (float*)d_out;

    cudaFuncSetAttribute(tconv_kernel,
                         cudaFuncAttributeMaxDynamicSharedMemorySize, DYN_SMEM);

    stats_kernel<<<STATS_BLOCKS, 256>>>(pre);
    prep_w_kernel<<<(TAPS * CI * CO_PAD + 255) / 256, 256>>>(lstmW);
    coef2_kernel<<<1, 192>>>(embW, embB, gamma, beta);
    dim3 cgrid(WW / TW, HH / TH, BB);   // (8, 32, 16) = 4096
    tconv_kernel<<<cgrid, CONV_THREADS, DYN_SMEM>>>(x, pre, h0, c0, outW, outB);
    sample_kernel<<<(BB * CC * HH * WW) / 256, 256>>>(x, out);
}

// round 11
// speedup vs baseline: 1.1459x; 1.1459x over previous
#include <cuda_runtime.h>
#include <cuda_bf16.h>
#include <math.h>
#include <stdint.h>

// ---------------- problem constants ----------------
#define BB 16
#define CC 16
#define HH 256
#define WW 256
#define NGF 16
#define PLANE 65536
#define NPIX (BB*PLANE)

// ---------------- conv tiling (R9-proven: 512 thr, 32x16 tile) ----------------
#define TW 32                 // tile width (px)
#define TH 16                 // tile height
#define MPX (TW*TH)           // 512 M rows
#define HALO_H 18
#define HALO_W 34
#define CI 48
#define CI_PAD 56             // bf16 elems per pixel (112 B)
#define PIX_STRIDE 112        // bytes
#define CO 64
#define CO_PAD 72             // bf16 elems per weight row (144 B)
#define W_ROW 144             // bytes
#define TAPS 9
#define IN_BYTES (HALO_H*HALO_W*PIX_STRIDE)      // 68,544
#define W_BYTES  (TAPS*CI*W_ROW)                 // 62,208
#define DYN_SMEM 133376
#define CONV_THREADS 512
#define NWARPS (CONV_THREADS/32)

#define STATS_BLOCKS 592

// ---------------- device scratch ----------------
__device__ double g_part[STATS_BLOCKS*5];
__device__ float  g_coef[3][NGF];
__device__ float  g_off[BB*2*PLANE];
__device__ __align__(16) unsigned short g_wb[TAPS*CI*CO_PAD];   // bf16 bits

// ---------------- helpers ----------------
__device__ __forceinline__ uint32_t smem_u32(const void* p) {
    uint32_t a;
    asm("{ .reg .u64 t; cvta.to.shared.u64 t, %1; cvt.u32.u64 %0, t; }"
        : "=r"(a) : "l"(p));
    return a;
}
__device__ __forceinline__ void ldm_x4(uint32_t r[4], uint32_t addr) {
    asm volatile("ldmatrix.sync.aligned.m8n8.x4.shared.b16 {%0,%1,%2,%3}, [%4];"
        : "=r"(r[0]), "=r"(r[1]), "=r"(r[2]), "=r"(r[3]) : "r"(addr));
}
__device__ __forceinline__ void ldm_x4t(uint32_t r[4], uint32_t addr) {
    asm volatile("ldmatrix.sync.aligned.m8n8.x4.trans.shared.b16 {%0,%1,%2,%3}, [%4];"
        : "=r"(r[0]), "=r"(r[1]), "=r"(r[2]), "=r"(r[3]) : "r"(addr));
}
__device__ __forceinline__ void mma_bf16(float d[4], const uint32_t a[4],
                                         const uint32_t b0, const uint32_t b1) {
    asm volatile(
        "mma.sync.aligned.m16n8k16.row.col.f32.bf16.bf16.f32 "
        "{%0,%1,%2,%3}, {%4,%5,%6,%7}, {%8,%9}, {%0,%1,%2,%3};"
        : "+f"(d[0]), "+f"(d[1]), "+f"(d[2]), "+f"(d[3])
        : "r"(a[0]), "r"(a[1]), "r"(a[2]), "r"(a[3]), "r"(b0), "r"(b1));
}
__inline__ __device__ double warp_sum(double v) {
    #pragma unroll
    for (int o = 16; o > 0; o >>= 1) v += __shfl_down_sync(0xffffffffu, v, o);
    return v;
}

// ---------------------------------------------------------------------------
// K1: 5-stat partial reduction over pre_offset (no atomics; per-block partials)
// ---------------------------------------------------------------------------
__global__ void stats_kernel(const float* __restrict__ pre) {
    double s[5] = {0, 0, 0, 0, 0};
    for (int i = blockIdx.x * blockDim.x + threadIdx.x; i < NPIX;
         i += gridDim.x * blockDim.x) {
        int b = i >> 16;
        int p = i & 65535;
        float p0 = pre[(b * 2) * PLANE + p];
        float p1 = pre[(b * 2 + 1) * PLANE + p];
        s[0] += p0; s[1] += p1;
        s[2] += (double)p0 * p0;
        s[3] += (double)p0 * p1;
        s[4] += (double)p1 * p1;
    }
    __shared__ double sh[8][5];
    const int w = threadIdx.x >> 5, l = threadIdx.x & 31;
    #pragma unroll
    for (int q = 0; q < 5; q++) {
        double v = warp_sum(s[q]);
        if (l == 0) sh[w][q] = v;
    }
    __syncthreads();
    if (threadIdx.x == 0) {
        #pragma unroll
        for (int q = 0; q < 5; q++) {
            double t = 0;
            for (int ww = 0; ww < 8; ww++) t += sh[ww][q];
            g_part[blockIdx.x * 5 + q] = t;
        }
    }
}

// ---------------------------------------------------------------------------
// K2: final reduce + fold 1x1 conv + BatchNorm into per-channel affine coefs
// ---------------------------------------------------------------------------
__global__ void coef2_kernel(const float* __restrict__ embW,
                             const float* __restrict__ embB,
                             const float* __restrict__ gamma,
                             const float* __restrict__ beta) {
    __shared__ double st[5];
    const int w = threadIdx.x >> 5, l = threadIdx.x & 31;
    if (w < 5) {
        double s = 0;
        for (int i = l; i < STATS_BLOCKS; i += 32) s += g_part[i * 5 + w];
        s = warp_sum(s);
        if (l == 0) st[w] = s;
    }
    __syncthreads();
    const int c = threadIdx.x;
    if (c >= NGF) return;
    const double N = (double)NPIX;
    double m0 = st[0] / N, m1 = st[1] / N;
    double v00 = st[2] / N - m0 * m0;
    double v01 = st[3] / N - m0 * m1;
    double v11 = st[4] / N - m1 * m1;
    double w0 = embW[c * 2 + 0], w1 = embW[c * 2 + 1];
    double var = w0 * w0 * v00 + 2.0 * w0 * w1 * v01 + w1 * w1 * v11;
    double mu = w0 * m0 + w1 * m1 + (double)embB[c];
    double scale = (double)gamma[c] * rsqrt(var + 1e-5);
    g_coef[0][c] = (float)(scale * w0);
    g_coef[1][c] = (float)(scale * w1);
    g_coef[2][c] = (float)((double)beta[c] + scale * ((double)embB[c] - mu));
}

// ---------------------------------------------------------------------------
// K3a: weight prep — fp32 [64co][48ci][3][3] -> bf16 [tap][ci][co_pad 72]
// ---------------------------------------------------------------------------
__global__ void prep_w_kernel(const float* __restrict__ lstmW) {
    int i = blockIdx.x * blockDim.x + threadIdx.x;
    if (i >= TAPS * CI * CO_PAD) return;
    int tap = i / (CI * CO_PAD);
    int r = i - tap * (CI * CO_PAD);
    int ci = r / CO_PAD;
    int co = r - ci * CO_PAD;
    float v = (co < CO) ? lstmW[co * (CI * 9) + ci * 9 + tap] : 0.f;
    g_wb[i] = __bfloat16_as_ushort(__float2bfloat16(v));
}

// ---------------------------------------------------------------------------
// K3b: HMMA fused conv + gates + offset head.
// CTA = 512 threads, 32x16 px tile, GEMM M=512 N=64 K=432. Grid = 2048.
// Warp tile: 64 px x 32 co. Mainloop fully unrolled (27 k-steps) for ILP.
// ---------------------------------------------------------------------------
extern __shared__ uint8_t cv_smem[];

__global__ void __launch_bounds__(CONV_THREADS, 1)
tconv_kernel(const float* __restrict__ x, const float* __restrict__ pre,
             const float* __restrict__ h0, const float* __restrict__ c0,
             const float* __restrict__ outW, const float* __restrict__ outB) {
    const int tid = threadIdx.x;
    const int lane = tid & 31;
    const int wid = tid >> 5;
    const int b = blockIdx.z;
    const int x0 = blockIdx.x * TW;
    const int y0 = blockIdx.y * TH;

    __nv_bfloat16* in_s16 = (__nv_bfloat16*)cv_smem;
    uint8_t* w_s = cv_smem + IN_BYTES;

    // ---- stage weights (L2-resident source) ----
    {
        const uint4* src = (const uint4*)g_wb;
        uint4* dst = (uint4*)w_s;
        #pragma unroll
        for (int i = tid; i < W_BYTES / 16; i += CONV_THREADS) dst[i] = src[i];
    }

    // ---- stage input tile, channel-last [y][x][ci] (thread per (y,ci),
    //      per-thread sequential x sweep — round-4 proven layout) ----
    for (int t = tid; t < HALO_H * CI; t += CONV_THREADS) {
        int y = t / CI, ci = t - y * CI;
        int gy = y0 + y - 1;
        bool yok = (gy >= 0 && gy < HH);
        const float* srcp;
        float ca = 0.f, cb2 = 0.f, cd = 0.f;
        int mode;
        if (ci < 16) { mode = 0; srcp = x + (b * 16 + ci) * PLANE; }
        else if (ci < 32) {
            mode = 1;
            int ce = ci - 16;
            ca = g_coef[0][ce]; cb2 = g_coef[1][ce]; cd = g_coef[2][ce];
            srcp = pre + (b * 2) * PLANE;
        } else { mode = 2; srcp = h0 + (b * 16 + (ci - 32)) * PLANE; }

        #pragma unroll 2
        for (int xi = 0; xi < HALO_W; xi++) {
            int gx = x0 + xi - 1;
            float v = 0.f;
            if (yok && gx >= 0 && gx < WW) {
                int pix = gy * WW + gx;
                if (mode == 1) {
                    float p0 = srcp[pix];
                    float p1 = srcp[PLANE + pix];
                    float e = fmaf(ca, p0, fmaf(cb2, p1, cd));
                    v = e > 0.f ? e : 0.2f * e;
                } else {
                    v = srcp[pix];
                }
            }
            in_s16[(y * HALO_W + xi) * CI_PAD + ci] = __float2bfloat16(v);
        }
    }
    __syncthreads();

    // ---- main HMMA loop (fully unrolled 27 k-steps) ----
    const int wm = wid >> 1;          // 0..7 : M block of 64 px (4 m16 tiles)
    const int wn = wid & 1;           // 0..1 : co group of 32

    float d[4][4][4];
    #pragma unroll
    for (int mt = 0; mt < 4; mt++)
        #pragma unroll
        for (int nt = 0; nt < 4; nt++)
            #pragma unroll
            for (int q = 0; q < 4; q++) d[mt][nt][q] = 0.f;

    const uint32_t in_base = smem_u32(cv_smem);
    // B via ldmatrix x4.trans dual-half addressing: lanes 0-15 -> first 8-co
    // pair, lanes 16-31 -> next 8-co pair (+16 B).
    const uint32_t w_base = in_base + IN_BYTES + (uint32_t)(wn * 32) * 2
                            + (uint32_t)((lane >> 4) * 16)
                            + (uint32_t)((lane & 15) * W_ROW);
    const int ar = lane & 15;         // A matrix row within tile
    const int kh = lane >> 4;         // A k-half

    #pragma unroll
    for (int tap = 0; tap < TAPS; tap++) {
        const int dy = tap / 3 - 1, dx = tap % 3 - 1;
        #pragma unroll
        for (int cig = 0; cig < 3; cig++) {
            const uint32_t brow = w_base +
                (uint32_t)(tap * (CI * W_ROW) + cig * 16 * W_ROW);
            uint32_t bf[8];
            ldm_x4t(bf,     brow);        // co [0..15]  (rel to wn*32)
            ldm_x4t(bf + 4, brow + 32);   // co [16..31]
            #pragma unroll
            for (int mt = 0; mt < 4; mt++) {
                const int gmt = wm * 4 + mt;            // 16-px tile index
                const int y_in = (gmt >> 1) + dy + 1;
                const int x_in = (gmt & 1) * 16 + ar + dx + 1;
                uint32_t aaddr = in_base +
                    (uint32_t)((y_in * HALO_W + x_in) * PIX_STRIDE
                               + cig * 32 + kh * 16);
                uint32_t a[4];
                ldm_x4(a, aaddr);
                mma_bf16(d[mt][0], a, bf[0], bf[1]);
                mma_bf16(d[mt][1], a, bf[2], bf[3]);
                mma_bf16(d[mt][2], a, bf[4], bf[5]);
                mma_bf16(d[mt][3], a, bf[6], bf[7]);
            }
        }
    }
    __syncthreads();

    // ---- exchange D through smem: A_ex[px][co], stride 65 ----
    float* A_ex = (float*)cv_smem;
    {
        const int row0 = lane >> 2;
        const int colb = (lane & 3) * 2;
        #pragma unroll
        for (int mt = 0; mt < 4; mt++) {
            const int gmt = wm * 4 + mt;
            #pragma unroll
            for (int nt = 0; nt < 4; nt++) {
                const int co = wn * 32 + nt * 8 + colb;
                const int p0 = gmt * 16 + row0;
                A_ex[p0 * 65 + co]       = d[mt][nt][0];
                A_ex[p0 * 65 + co + 1]   = d[mt][nt][1];
                A_ex[(p0 + 8) * 65 + co]     = d[mt][nt][2];
                A_ex[(p0 + 8) * 65 + co + 1] = d[mt][nt][3];
            }
        }
    }
    __syncthreads();

    // ---- gates + offset head, one pixel per thread ----
    {
        const int p = tid;
        const int py = y0 + (p >> 5);
        const int pxx = x0 + (p & 31);
        const int pix = py * WW + pxx;
        const float* Ap = A_ex + p * 65;
        float off0 = outB[0], off1 = outB[1];
        #pragma unroll
        for (int ch = 0; ch < 16; ch++) {
            float ai = Ap[ch];
            float af = Ap[16 + ch];
            float ao = Ap[32 + ch];
            float ag = Ap[48 + ch];
            float iv = 1.f / (1.f + __expf(-ai));
            float fv = 1.f / (1.f + __expf(-af));
            float ov = 1.f / (1.f + __expf(-ao));
            float gv = tanhf(ag);
            float c0v = c0[(b * 16 + ch) * PLANE + pix];
            float c1 = fv * c0v + iv * gv;
            float hv = ov * tanhf(c1);
            off0 = fmaf(outW[ch], hv, off0);
            off1 = fmaf(outW[16 + ch], hv, off1);
        }
        g_off[(b * 2) * PLANE + pix] = off0;
        g_off[(b * 2 + 1) * PLANE + pix] = off1;
    }
}

// ---------------------------------------------------------------------------
// K4: bilinear warp (torch-.view pair semantics: flat indices 2p, 2p+1)
// ---------------------------------------------------------------------------
__global__ void sample_kernel(const float* __restrict__ x,
                              float* __restrict__ out) {
    int n = blockIdx.x * blockDim.x + threadIdx.x;
    int pix = n & 65535;
    int bc = n >> 16;
    int b = bc >> 4;
    int hh = pix >> 8;
    int ww = pix & 255;

    const float2* offb = (const float2*)(g_off + b * 2 * PLANE);
    float2 offp = offb[pix];
    float off0 = offp.x;
    float off1 = offp.y;

    float yc = fminf(fmaxf((float)hh + off0, 0.f), 255.f);
    float xc = fminf(fmaxf((float)ww + off1, 0.f), 255.f);
    float y0f = floorf(yc);
    float x0f = floorf(xc);
    int y0 = (int)y0f;
    int x0 = (int)x0f;
    int y1 = min(y0 + 1, 255);
    int x1 = min(x0 + 1, 255);
    float dy = yc - y0f;
    float dx = xc - x0f;

    const float* img = x + bc * PLANE;
    float v00 = img[y0 * WW + x0];
    float v01 = img[y0 * WW + x1];
    float v10 = img[y1 * WW + x0];
    float v11 = img[y1 * WW + x1];
    float top = v00 + (v01 - v00) * dx;
    float bot = v10 + (v11 - v10) * dx;
    out[n] = top + (bot - top) * dy;
}

// ---------------------------------------------------------------------------
extern "C" void kernel_launch(void* const* d_in, const int* in_sizes, int n_in,
                              void* d_out, int out_size) {
    const float* x     = (const float*)d_in[0];
    const float* pre   = (const float*)d_in[1];
    const float* h0    = (const float*)d_in[2];
    const float* c0    = (const float*)d_in[3];
    const float* embW  = (const float*)d_in[4];
    const float* embB  = (const float*)d_in[5];
    const float* gamma = (const float*)d_in[6];
    const float* beta  = (const float*)d_in[7];
    const float* lstmW = (const float*)d_in[8];
    const float* outW  = (const float*)d_in[9];
    const float* outB  = (const float*)d_in[10];
    float* out = (float*)d_out;

    cudaFuncSetAttribute(tconv_kernel,
                         cudaFuncAttributeMaxDynamicSharedMemorySize, DYN_SMEM);

    stats_kernel<<<STATS_BLOCKS, 256>>>(pre);
    prep_w_kernel<<<(TAPS * CI * CO_PAD + 255) / 256, 256>>>(lstmW);
    coef2_kernel<<<1, 192>>>(embW, embB, gamma, beta);
    dim3 cgrid(WW / TW, HH / TH, BB);   // (8, 16, 16) = 2048
    tconv_kernel<<<cgrid, CONV_THREADS, DYN_SMEM>>>(x, pre, h0, c0, outW, outB);
    sample_kernel<<<(BB * CC * HH * WW) / 256, 256>>>(x, out);
}

// round 12
// speedup vs baseline: 1.4419x; 1.2583x over previous
#include <cuda_runtime.h>
#include <cuda_bf16.h>
#include <math.h>
#include <stdint.h>

// ---------------- problem constants ----------------
#define BB 16
#define CC 16
#define HH 256
#define WW 256
#define NGF 16
#define PLANE 65536
#define NPIX (BB*PLANE)

// ---------------- conv tiling (512 thr, 32x16 tile) ----------------
#define TW 32
#define TH 16
#define MPX (TW*TH)
#define HALO_H 18
#define HALO_W 34
#define CI 48
#define CI_PAD 56             // bf16 elems per pixel (112 B)
#define PIX_STRIDE 112        // bytes
#define CO 64
#define CO_PAD 72
#define W_ROW 144             // bytes
#define TAPS 9
#define XG 10                 // 4-px groups covering halo width
#define IN_BYTES (HALO_H*HALO_W*PIX_STRIDE)      // 68,544
#define W_BYTES  (TAPS*CI*W_ROW)                 // 62,208
#define DYN_SMEM 133376
#define CONV_THREADS 512
#define STATS_BLOCKS 592

// ---------------- device scratch ----------------
__device__ double g_part[STATS_BLOCKS*5];
__device__ float  g_coef[3][NGF];
__device__ float  g_off[BB*2*PLANE];
__device__ __align__(16) unsigned short g_wb[TAPS*CI*CO_PAD];   // bf16 bits

// ---------------- helpers ----------------
__device__ __forceinline__ uint32_t smem_u32(const void* p) {
    uint32_t a;
    asm("{ .reg .u64 t; cvta.to.shared.u64 t, %1; cvt.u32.u64 %0, t; }"
        : "=r"(a) : "l"(p));
    return a;
}
__device__ __forceinline__ void ldm_x4(uint32_t r[4], uint32_t addr) {
    asm volatile("ldmatrix.sync.aligned.m8n8.x4.shared.b16 {%0,%1,%2,%3}, [%4];"
        : "=r"(r[0]), "=r"(r[1]), "=r"(r[2]), "=r"(r[3]) : "r"(addr));
}
__device__ __forceinline__ void ldm_x4t(uint32_t r[4], uint32_t addr) {
    asm volatile("ldmatrix.sync.aligned.m8n8.x4.trans.shared.b16 {%0,%1,%2,%3}, [%4];"
        : "=r"(r[0]), "=r"(r[1]), "=r"(r[2]), "=r"(r[3]) : "r"(addr));
}
__device__ __forceinline__ void mma_bf16(float d[4], const uint32_t a[4],
                                         const uint32_t b0, const uint32_t b1) {
    asm volatile(
        "mma.sync.aligned.m16n8k16.row.col.f32.bf16.bf16.f32 "
        "{%0,%1,%2,%3}, {%4,%5,%6,%7}, {%8,%9}, {%0,%1,%2,%3};"
        : "+f"(d[0]), "+f"(d[1]), "+f"(d[2]), "+f"(d[3])
        : "r"(a[0]), "r"(a[1]), "r"(a[2]), "r"(a[3]), "r"(b0), "r"(b1));
}
__inline__ __device__ double warp_sum(double v) {
    #pragma unroll
    for (int o = 16; o > 0; o >>= 1) v += __shfl_down_sync(0xffffffffu, v, o);
    return v;
}
__device__ __forceinline__ uint32_t pack_bf16(float lo, float hi) {
    __nv_bfloat16 l = __float2bfloat16(lo);
    __nv_bfloat16 h = __float2bfloat16(hi);
    return (uint32_t)__bfloat16_as_ushort(l) | ((uint32_t)__bfloat16_as_ushort(h) << 16);
}
// guarded aligned float4 row load (row = plane + gy*WW), gxb multiple of 4
__device__ __forceinline__ float4 ld4g(const float* __restrict__ row, int gxb) {
    if (gxb >= 0 && gxb + 3 < WW) return *(const float4*)(row + gxb);
    float4 r;
    r.x = (gxb + 0 >= 0 && gxb + 0 < WW) ? row[gxb + 0] : 0.f;
    r.y = (gxb + 1 >= 0 && gxb + 1 < WW) ? row[gxb + 1] : 0.f;
    r.z = (gxb + 2 >= 0 && gxb + 2 < WW) ? row[gxb + 2] : 0.f;
    r.w = (gxb + 3 >= 0 && gxb + 3 < WW) ? row[gxb + 3] : 0.f;
    return r;
}

// ---------------------------------------------------------------------------
// K1: 5-stat partial reduction over pre_offset
// ---------------------------------------------------------------------------
__global__ void stats_kernel(const float* __restrict__ pre) {
    double s[5] = {0, 0, 0, 0, 0};
    for (int i = blockIdx.x * blockDim.x + threadIdx.x; i < NPIX;
         i += gridDim.x * blockDim.x) {
        int b = i >> 16;
        int p = i & 65535;
        float p0 = pre[(b * 2) * PLANE + p];
        float p1 = pre[(b * 2 + 1) * PLANE + p];
        s[0] += p0; s[1] += p1;
        s[2] += (double)p0 * p0;
        s[3] += (double)p0 * p1;
        s[4] += (double)p1 * p1;
    }
    __shared__ double sh[8][5];
    const int w = threadIdx.x >> 5, l = threadIdx.x & 31;
    #pragma unroll
    for (int q = 0; q < 5; q++) {
        double v = warp_sum(s[q]);
        if (l == 0) sh[w][q] = v;
    }
    __syncthreads();
    if (threadIdx.x == 0) {
        #pragma unroll
        for (int q = 0; q < 5; q++) {
            double t = 0;
            for (int ww = 0; ww < 8; ww++) t += sh[ww][q];
            g_part[blockIdx.x * 5 + q] = t;
        }
    }
}

// ---------------------------------------------------------------------------
// K2: final reduce + BN fold
// ---------------------------------------------------------------------------
__global__ void coef2_kernel(const float* __restrict__ embW,
                             const float* __restrict__ embB,
                             const float* __restrict__ gamma,
                             const float* __restrict__ beta) {
    __shared__ double st[5];
    const int w = threadIdx.x >> 5, l = threadIdx.x & 31;
    if (w < 5) {
        double s = 0;
        for (int i = l; i < STATS_BLOCKS; i += 32) s += g_part[i * 5 + w];
        s = warp_sum(s);
        if (l == 0) st[w] = s;
    }
    __syncthreads();
    const int c = threadIdx.x;
    if (c >= NGF) return;
    const double N = (double)NPIX;
    double m0 = st[0] / N, m1 = st[1] / N;
    double v00 = st[2] / N - m0 * m0;
    double v01 = st[3] / N - m0 * m1;
    double v11 = st[4] / N - m1 * m1;
    double w0 = embW[c * 2 + 0], w1 = embW[c * 2 + 1];
    double var = w0 * w0 * v00 + 2.0 * w0 * w1 * v01 + w1 * w1 * v11;
    double mu = w0 * m0 + w1 * m1 + (double)embB[c];
    double scale = (double)gamma[c] * rsqrt(var + 1e-5);
    g_coef[0][c] = (float)(scale * w0);
    g_coef[1][c] = (float)(scale * w1);
    g_coef[2][c] = (float)((double)beta[c] + scale * ((double)embB[c] - mu));
}

// ---------------------------------------------------------------------------
// K3a: weight prep — fp32 [64co][48ci][3][3] -> bf16 [tap][ci][co_pad 72]
// ---------------------------------------------------------------------------
__global__ void prep_w_kernel(const float* __restrict__ lstmW) {
    int i = blockIdx.x * blockDim.x + threadIdx.x;
    if (i >= TAPS * CI * CO_PAD) return;
    int tap = i / (CI * CO_PAD);
    int r = i - tap * (CI * CO_PAD);
    int ci = r / CO_PAD;
    int co = r - ci * CO_PAD;
    float v = (co < CO) ? lstmW[co * (CI * 9) + ci * 9 + tap] : 0.f;
    g_wb[i] = __bfloat16_as_ushort(__float2bfloat16(v));
}

// ---------------------------------------------------------------------------
// K3b: HMMA fused conv + gates + offset head. 512 thr, 32x16 tile, grid 2048.
// Staging: vectorized transpose (thread = (y, 4ci, 4x); x-fastest lanes).
// ---------------------------------------------------------------------------
extern __shared__ uint8_t cv_smem[];

__global__ void __launch_bounds__(CONV_THREADS, 1)
tconv_kernel(const float* __restrict__ x, const float* __restrict__ pre,
             const float* __restrict__ h0, const float* __restrict__ c0,
             const float* __restrict__ outW, const float* __restrict__ outB) {
    const int tid = threadIdx.x;
    const int lane = tid & 31;
    const int wid = tid >> 5;
    const int b = blockIdx.z;
    const int x0 = blockIdx.x * TW;
    const int y0 = blockIdx.y * TH;

    uint8_t* w_s = cv_smem + IN_BYTES;

    // ---- stage weights (L2-resident source) ----
    {
        const uint4* src = (const uint4*)g_wb;
        uint4* dst = (uint4*)w_s;
        #pragma unroll
        for (int i = tid; i < W_BYTES / 16; i += CONV_THREADS) dst[i] = src[i];
    }

    // ---- stage input tile, channel-last [y][x][ci]: vectorized transpose.
    // Task = (y, c4 in 0..11, xg in 0..9); xg fastest -> coalesced float4 LDG;
    // stores 4x 8B (4 bf16 channels) per x position.
    for (int t = tid; t < HALO_H * 12 * XG; t += CONV_THREADS) {
        const int xg = t % XG;
        const int rem = t / XG;
        const int c4 = rem % 12;
        const int y = rem / 12;
        const int gy = y0 + y - 1;
        const int gxb = x0 - 4 + xg * 4;

        float v[4][4];                    // [cl][j]
        #pragma unroll
        for (int cl = 0; cl < 4; cl++)
            #pragma unroll
            for (int j = 0; j < 4; j++) v[cl][j] = 0.f;

        if (gy >= 0 && gy < HH) {
            if (c4 < 4 || c4 >= 8) {
                const float* plane = (c4 < 4)
                    ? (x + (size_t)(b * 16 + c4 * 4) * PLANE)
                    : (h0 + (size_t)(b * 16 + (c4 * 4 - 32)) * PLANE);
                #pragma unroll
                for (int cl = 0; cl < 4; cl++) {
                    float4 q = ld4g(plane + (size_t)cl * PLANE + gy * WW, gxb);
                    v[cl][0] = q.x; v[cl][1] = q.y; v[cl][2] = q.z; v[cl][3] = q.w;
                }
            } else {
                const float* p0r = pre + (size_t)(b * 2) * PLANE + gy * WW;
                float4 q0 = ld4g(p0r, gxb);
                float4 q1 = ld4g(p0r + PLANE, gxb);
                float a0[4] = {q0.x, q0.y, q0.z, q0.w};
                float a1[4] = {q1.x, q1.y, q1.z, q1.w};
                #pragma unroll
                for (int cl = 0; cl < 4; cl++) {
                    const int ce = c4 * 4 + cl - 16;
                    const float ca = g_coef[0][ce], cb2 = g_coef[1][ce],
                                cd = g_coef[2][ce];
                    #pragma unroll
                    for (int j = 0; j < 4; j++) {
                        float e = fmaf(ca, a0[j], fmaf(cb2, a1[j], cd));
                        v[cl][j] = e > 0.f ? e : 0.2f * e;
                    }
                }
            }
        }
        #pragma unroll
        for (int j = 0; j < 4; j++) {
            const int xi = xg * 4 - 3 + j;
            if (xi >= 0 && xi < HALO_W) {
                uint2 w2;
                w2.x = pack_bf16(v[0][j], v[1][j]);
                w2.y = pack_bf16(v[2][j], v[3][j]);
                *(uint2*)(cv_smem + (y * HALO_W + xi) * PIX_STRIDE + c4 * 8) = w2;
            }
        }
    }
    __syncthreads();

    // ---- main HMMA loop (fully unrolled 27 k-steps) ----
    const int wm = wid >> 1;          // 0..7 : M block of 64 px
    const int wn = wid & 1;           // 0..1 : co group of 32

    float d[4][4][4];
    #pragma unroll
    for (int mt = 0; mt < 4; mt++)
        #pragma unroll
        for (int nt = 0; nt < 4; nt++)
            #pragma unroll
            for (int q = 0; q < 4; q++) d[mt][nt][q] = 0.f;

    const uint32_t in_base = smem_u32(cv_smem);
    const uint32_t w_base = in_base + IN_BYTES + (uint32_t)(wn * 32) * 2
                            + (uint32_t)((lane >> 4) * 16)
                            + (uint32_t)((lane & 15) * W_ROW);
    const int ar = lane & 15;
    const int kh = lane >> 4;

    #pragma unroll
    for (int tap = 0; tap < TAPS; tap++) {
        const int dy = tap / 3 - 1, dx = tap % 3 - 1;
        #pragma unroll
        for (int cig = 0; cig < 3; cig++) {
            const uint32_t brow = w_base +
                (uint32_t)(tap * (CI * W_ROW) + cig * 16 * W_ROW);
            uint32_t bf[8];
            ldm_x4t(bf,     brow);
            ldm_x4t(bf + 4, brow + 32);
            #pragma unroll
            for (int mt = 0; mt < 4; mt++) {
                const int gmt = wm * 4 + mt;
                const int y_in = (gmt >> 1) + dy + 1;
                const int x_in = (gmt & 1) * 16 + ar + dx + 1;
                uint32_t aaddr = in_base +
                    (uint32_t)((y_in * HALO_W + x_in) * PIX_STRIDE
                               + cig * 32 + kh * 16);
                uint32_t a[4];
                ldm_x4(a, aaddr);
                mma_bf16(d[mt][0], a, bf[0], bf[1]);
                mma_bf16(d[mt][1], a, bf[2], bf[3]);
                mma_bf16(d[mt][2], a, bf[4], bf[5]);
                mma_bf16(d[mt][3], a, bf[6], bf[7]);
            }
        }
    }
    __syncthreads();

    // ---- exchange D through smem: A_ex[px][co], stride 65 ----
    float* A_ex = (float*)cv_smem;
    {
        const int row0 = lane >> 2;
        const int colb = (lane & 3) * 2;
        #pragma unroll
        for (int mt = 0; mt < 4; mt++) {
            const int gmt = wm * 4 + mt;
            #pragma unroll
            for (int nt = 0; nt < 4; nt++) {
                const int co = wn * 32 + nt * 8 + colb;
                const int p0 = gmt * 16 + row0;
                A_ex[p0 * 65 + co]       = d[mt][nt][0];
                A_ex[p0 * 65 + co + 1]   = d[mt][nt][1];
                A_ex[(p0 + 8) * 65 + co]     = d[mt][nt][2];
                A_ex[(p0 + 8) * 65 + co + 1] = d[mt][nt][3];
            }
        }
    }
    __syncthreads();

    // ---- gates + offset head, one pixel per thread ----
    {
        const int p = tid;
        const int py = y0 + (p >> 5);
        const int pxx = x0 + (p & 31);
        const int pix = py * WW + pxx;
        const float* Ap = A_ex + p * 65;
        float off0 = outB[0], off1 = outB[1];
        #pragma unroll
        for (int ch = 0; ch < 16; ch++) {
            float ai = Ap[ch];
            float af = Ap[16 + ch];
            float ao = Ap[32 + ch];
            float ag = Ap[48 + ch];
            float iv = 1.f / (1.f + __expf(-ai));
            float fv = 1.f / (1.f + __expf(-af));
            float ov = 1.f / (1.f + __expf(-ao));
            float gv = tanhf(ag);
            float c0v = c0[(b * 16 + ch) * PLANE + pix];
            float c1 = fv * c0v + iv * gv;
            float hv = ov * tanhf(c1);
            off0 = fmaf(outW[ch], hv, off0);
            off1 = fmaf(outW[16 + ch], hv, off1);
        }
        g_off[(b * 2) * PLANE + pix] = off0;
        g_off[(b * 2 + 1) * PLANE + pix] = off1;
    }
}

// ---------------------------------------------------------------------------
// K4: bilinear warp (torch-.view pair semantics: flat indices 2p, 2p+1)
// ---------------------------------------------------------------------------
__global__ void sample_kernel(const float* __restrict__ x,
                              float* __restrict__ out) {
    int n = blockIdx.x * blockDim.x + threadIdx.x;
    int pix = n & 65535;
    int bc = n >> 16;
    int b = bc >> 4;
    int hh = pix >> 8;
    int ww = pix & 255;

    const float2* offb = (const float2*)(g_off + b * 2 * PLANE);
    float2 offp = offb[pix];
    float off0 = offp.x;
    float off1 = offp.y;

    float yc = fminf(fmaxf((float)hh + off0, 0.f), 255.f);
    float xc = fminf(fmaxf((float)ww + off1, 0.f), 255.f);
    float y0f = floorf(yc);
    float x0f = floorf(xc);
    int y0 = (int)y0f;
    int x0 = (int)x0f;
    int y1 = min(y0 + 1, 255);
    int x1 = min(x0 + 1, 255);
    float dy = yc - y0f;
    float dx = xc - x0f;

    const float* img = x + bc * PLANE;
    float v00 = img[y0 * WW + x0];
    float v01 = img[y0 * WW + x1];
    float v10 = img[y1 * WW + x0];
    float v11 = img[y1 * WW + x1];
    float top = v00 + (v01 - v00) * dx;
    float bot = v10 + (v11 - v10) * dx;
    out[n] = top + (bot - top) * dy;
}

// ---------------------------------------------------------------------------
extern "C" void kernel_launch(void* const* d_in, const int* in_sizes, int n_in,
                              void* d_out, int out_size) {
    const float* x     = (const float*)d_in[0];
    const float* pre   = (const float*)d_in[1];
    const float* h0    = (const float*)d_in[2];
    const float* c0    = (const float*)d_in[3];
    const float* embW  = (const float*)d_in[4];
    const float* embB  = (const float*)d_in[5];
    const float* gamma = (const float*)d_in[6];
    const float* beta  = (const float*)d_in[7];
    const float* lstmW = (const float*)d_in[8];
    const float* outW  = (const float*)d_in[9];
    const float* outB  = (const float*)d_in[10];
    float* out = (float*)d_out;

    cudaFuncSetAttribute(tconv_kernel,
                         cudaFuncAttributeMaxDynamicSharedMemorySize, DYN_SMEM);

    stats_kernel<<<STATS_BLOCKS, 256>>>(pre);
    prep_w_kernel<<<(TAPS * CI * CO_PAD + 255) / 256, 256>>>(lstmW);
    coef2_kernel<<<1, 192>>>(embW, embB, gamma, beta);
    dim3 cgrid(WW / TW, HH / TH, BB);   // (8, 16, 16) = 2048
    tconv_kernel<<<cgrid, CONV_THREADS, DYN_SMEM>>>(x, pre, h0, c0, outW, outB);
    sample_kernel<<<(BB * CC * HH * WW) / 256, 256>>>(x, out);
}